// round 15
// baseline (speedup 1.0000x reference)
#include <cuda_runtime.h>
#include <cstdint>

#define BSZ 512
#define VV  30000
#define K0  128
#define EPSF 2.2e-10f
#define MBR 100.0f
#define NZ0 37
#define NBF 48
#define NTF 256
#define NTOT (NBF * NTF)
#define NSN 148

// ---------------- scratch (device globals: allocation-free) ----------------
__device__ float g_ratio[VV * BSZ];
__device__ float g_phiR[VV * K0];
__device__ float g_thR[K0 * BSZ];
__device__ float g_W[VV * K0];
__device__ float g_part[NZ0 * K0 * BSZ];
__device__ float g_xa[K0 * BSZ];
__device__ float g_xb[K0 * BSZ];
__device__ float g_ratio1[K0 * BSZ];
__device__ float g_ratio2[64 * BSZ];
__device__ float g_W1[K0 * 64];
__device__ float g_W2[64 * 32];
__device__ float g_S[384];
__device__ float g_P[384];
__device__ float g_phisum[384];
__device__ float g_qsum[384];
__device__ unsigned g_barcnt;
__device__ unsigned g_bargen;
__device__ unsigned g_barcnt2;
__device__ unsigned g_bargen2;

// ---------------- digamma (fast) ----------------
__device__ __forceinline__ float digammaf_(float x) {
    float r = 0.f;
    while (x < 6.f) { r -= __fdividef(1.f, x); x += 1.f; }
    float inv  = __fdividef(1.f, x);
    float inv2 = inv * inv;
    float ser  = inv2 * (0.08333333333f - inv2 * (0.008333333333f - inv2 * 0.003968253968f));
    return r + logf(x) - 0.5f * inv - ser;
}

// ---------------- tf32 + mma + cp.async helpers ----------------
__device__ __forceinline__ uint32_t to_tf32(float x) {
    uint32_t r;
    asm("cvt.rna.tf32.f32 %0, %1;" : "=r"(r) : "f"(x));
    return r;
}

__device__ __forceinline__ void mma8(float* d,
                                     uint32_t a0, uint32_t a1, uint32_t a2, uint32_t a3,
                                     uint32_t b0, uint32_t b1) {
    asm volatile(
        "mma.sync.aligned.m16n8k8.row.col.f32.tf32.tf32.f32 "
        "{%0,%1,%2,%3},{%4,%5,%6,%7},{%8,%9},{%0,%1,%2,%3};\n"
        : "+f"(d[0]), "+f"(d[1]), "+f"(d[2]), "+f"(d[3])
        : "r"(a0), "r"(a1), "r"(a2), "r"(a3), "r"(b0), "r"(b1));
}

__device__ __forceinline__ void cpa16(uint32_t* s, const void* gsrc, bool v) {
    uint32_t sa = (uint32_t)__cvta_generic_to_shared(s);
    int sz = v ? 16 : 0;
    asm volatile("cp.async.cg.shared.global [%0], [%1], 16, %2;\n"
                 :: "r"(sa), "l"(gsrc), "r"(sz) : "memory");
}
#define CP_COMMIT() asm volatile("cp.async.commit_group;\n" ::: "memory")
#define CP_WAIT1()  asm volatile("cp.async.wait_group 1;\n" ::: "memory")
#define CP_WAIT0()  asm volatile("cp.async.wait_group 0;\n" ::: "memory")

// ---- BK=32 k-tile variants for 128x64 block tiles (acc[2][4][4]) ----
// A [m][k] stride 36, B [k][n] stride 68
__device__ __forceinline__ void kt_mk_kn64(
    const uint32_t* __restrict__ As, const uint32_t* __restrict__ Bs,
    int wm, int wn, int g, int c, float acc[2][4][4]) {
#pragma unroll
    for (int k8 = 0; k8 < 4; k8++) {
        const int k0 = k8 * 8;
        uint32_t a[2][4];
#pragma unroll
        for (int mt = 0; mt < 2; mt++) {
            int r = wm * 32 + mt * 16 + g;
            a[mt][0] = As[r * 36 + k0 + c];
            a[mt][1] = As[(r + 8) * 36 + k0 + c];
            a[mt][2] = As[r * 36 + k0 + c + 4];
            a[mt][3] = As[(r + 8) * 36 + k0 + c + 4];
        }
#pragma unroll
        for (int nt = 0; nt < 4; nt++) {
            int n = wn * 32 + nt * 8 + g;
            uint32_t b0 = Bs[(k0 + c) * 68 + n];
            uint32_t b1 = Bs[(k0 + c + 4) * 68 + n];
#pragma unroll
            for (int mt = 0; mt < 2; mt++)
                mma8(acc[mt][nt], a[mt][0], a[mt][1], a[mt][2], a[mt][3], b0, b1);
        }
    }
}
// A [m][k] stride 36, B [n][k] stride 36 (n local 0..63)
__device__ __forceinline__ void kt_mk_nk64(
    const uint32_t* __restrict__ As, const uint32_t* __restrict__ Bs,
    int wm, int wn, int g, int c, float acc[2][4][4]) {
#pragma unroll
    for (int k8 = 0; k8 < 4; k8++) {
        const int k0 = k8 * 8;
        uint32_t a[2][4];
#pragma unroll
        for (int mt = 0; mt < 2; mt++) {
            int r = wm * 32 + mt * 16 + g;
            a[mt][0] = As[r * 36 + k0 + c];
            a[mt][1] = As[(r + 8) * 36 + k0 + c];
            a[mt][2] = As[r * 36 + k0 + c + 4];
            a[mt][3] = As[(r + 8) * 36 + k0 + c + 4];
        }
#pragma unroll
        for (int nt = 0; nt < 4; nt++) {
            int n = wn * 32 + nt * 8 + g;
            uint32_t b0 = Bs[n * 36 + k0 + c];
            uint32_t b1 = Bs[n * 36 + k0 + c + 4];
#pragma unroll
            for (int mt = 0; mt < 2; mt++)
                mma8(acc[mt][nt], a[mt][0], a[mt][1], a[mt][2], a[mt][3], b0, b1);
        }
    }
}
// A [k][m] stride 132, B [k][n] stride 68
__device__ __forceinline__ void kt_km_kn64(
    const uint32_t* __restrict__ As, const uint32_t* __restrict__ Bs,
    int wm, int wn, int g, int c, float acc[2][4][4]) {
#pragma unroll
    for (int k8 = 0; k8 < 4; k8++) {
        const int k0 = k8 * 8;
        uint32_t a[2][4];
#pragma unroll
        for (int mt = 0; mt < 2; mt++) {
            int r = wm * 32 + mt * 16 + g;
            a[mt][0] = As[(k0 + c) * 132 + r];
            a[mt][1] = As[(k0 + c) * 132 + r + 8];
            a[mt][2] = As[(k0 + c + 4) * 132 + r];
            a[mt][3] = As[(k0 + c + 4) * 132 + r + 8];
        }
#pragma unroll
        for (int nt = 0; nt < 4; nt++) {
            int n = wn * 32 + nt * 8 + g;
            uint32_t b0 = Bs[(k0 + c) * 68 + n];
            uint32_t b1 = Bs[(k0 + c + 4) * 68 + n];
#pragma unroll
            for (int mt = 0; mt < 2; mt++)
                mma8(acc[mt][nt], a[mt][0], a[mt][1], a[mt][2], a[mt][3], b0, b1);
        }
    }
}

// ---------------- zero all slot accumulators ----------------
__global__ void zero384_kernel(float* S, float* P, float* PS, float* QS) {
    int i = threadIdx.x;
    S[i] = 0.f; P[i] = 0.f; PS[i] = 0.f; QS[i] = 0.f;
}

// ---------------- combined colstats for 3 layers ----------------
__global__ void colstats3_kernel(
    const float* __restrict__ p0, const float* __restrict__ n0,
    const float* __restrict__ p1, const float* __restrict__ n1,
    const float* __restrict__ p2, const float* __restrict__ n2,
    float* __restrict__ phisum, float* __restrict__ qsum) {
    int b = blockIdx.x;
    const float *phi, *noise; int DK, K, base; float *ps, *qs;
    if (b < 938)      { phi = p0; noise = n0; DK = VV * 128; K = 128; base = b * 4096;        ps = phisum;       qs = qsum; }
    else if (b < 940) { phi = p1; noise = n1; DK = 128 * 64; K = 64;  base = (b - 938) * 4096; ps = phisum + 128; qs = qsum + 128; }
    else              { phi = p2; noise = n2; DK = 64 * 32;  K = 32;  base = 0;               ps = phisum + 256; qs = qsum + 256; }
    __shared__ float sA[128], sB[128];
    int tid = threadIdx.x;
    if (tid < K) { sA[tid] = 0.f; sB[tid] = 0.f; }
    __syncthreads();
    int k = (base + tid) & (K - 1);
    float pa = 0.f, pb = 0.f;
#pragma unroll 4
    for (int e = 0; e < 16; e++) {
        int idx = base + e * 256 + tid;
        if (idx < DK) {
            float ph = phi[idx], nz = noise[idx];
            pa += ph;
            pb += sqrtf(ph) * nz;
        }
    }
    atomicAdd(&sA[k], pa);
    atomicAdd(&sB[k], pb);
    __syncthreads();
    if (tid < K) { atomicAdd(&ps[tid], sA[tid]); atomicAdd(&qs[tid], sB[tid]); }
}

// ---------------- pre-round phi0/theta0 to tf32 ----------------
__global__ void preround_kernel(const float* __restrict__ a, uint32_t* __restrict__ oa, int n4a,
                                const float* __restrict__ b, uint32_t* __restrict__ ob, int n4b) {
    int i = blockIdx.x * 256 + threadIdx.x;
    if (i < n4a) {
        float4 v = ((const float4*)a)[i];
        uint4 o = {to_tf32(v.x), to_tf32(v.y), to_tf32(v.z), to_tf32(v.w)};
        ((uint4*)oa)[i] = o;
    } else if (i < n4a + n4b) {
        int j = i - n4a;
        float4 v = ((const float4*)b)[j];
        uint4 o = {to_tf32(v.x), to_tf32(v.y), to_tf32(v.z), to_tf32(v.w)};
        ((uint4*)ob)[j] = o;
    }
}

// ============================================================================
// Layer-0 GEMMs: 128x64 tiles, 2-stage cp.async, 3 CTAs/SM
// ============================================================================
#define G1_ASZ (128 * 36)
#define G1_BSZ (32 * 68)
#define G1_STAGE (G1_ASZ + G1_BSZ)
#define G2_ASZ (128 * 36)
#define G2_BSZ (64 * 36)
#define G2_STAGE (G2_ASZ + G2_BSZ)
#define G3_ASZ (32 * 132)
#define G3_BSZ (32 * 68)
#define G3_STAGE (G3_ASZ + G3_BSZ)

// GEMM1: denom = phiR@thR; ratio = tf32(x/denom); x read directly (B,V layout)
__global__ __launch_bounds__(256, 3) void ratio_gemm_tc(
    const float* __restrict__ phiR, const float* __restrict__ thR,
    const float* __restrict__ x, float* __restrict__ ratio) {
    extern __shared__ uint32_t dsm[];
    const int bn = blockIdx.x * 64, bv = blockIdx.y * 128;
    const int tid = threadIdx.x;
    const int wid = tid >> 5, lane = tid & 31;
    const int wm = wid >> 1, wn = wid & 1;
    const int g = lane >> 2, c = lane & 3;
    float acc[2][4][4] = {};

    auto loadT = [&](int kk, int buf) {
        uint32_t* As = dsm + buf * G1_STAGE;
        uint32_t* Bs = As + G1_ASZ;
#pragma unroll
        for (int e = 0; e < 4; e++) {            // A: 128 rows x 32 (8 f4/row)
            int idx = tid + e * 256;
            int m = idx >> 3, c4 = idx & 7;
            bool v = (bv + m) < VV;
            const float* src = v ? &phiR[(size_t)(bv + m) * 128 + kk + c4 * 4] : phiR;
            cpa16(&As[m * 36 + c4 * 4], src, v);
        }
#pragma unroll
        for (int e = 0; e < 2; e++) {            // B: 32 rows x 64 (16 f4/row)
            int idx = tid + e * 256;
            int r = idx >> 4, c4 = idx & 15;
            cpa16(&Bs[r * 68 + c4 * 4], &thR[(kk + r) * BSZ + bn + c4 * 4], true);
        }
        CP_COMMIT();
    };

    loadT(0, 0);
#pragma unroll
    for (int kt = 0; kt < 4; kt++) {
        int cur = kt & 1;
        if (kt < 3) { loadT((kt + 1) * 32, cur ^ 1); CP_WAIT1(); }
        else        { CP_WAIT0(); }
        __syncthreads();
        uint32_t* As = dsm + cur * G1_STAGE;
        kt_mk_kn64(As, As + G1_ASZ, wm, wn, g, c, acc);
        __syncthreads();
    }
#pragma unroll
    for (int mt = 0; mt < 2; mt++)
#pragma unroll
        for (int half = 0; half < 2; half++) {
            int v = bv + wm * 32 + mt * 16 + g + half * 8;
            if (v >= VV) continue;
#pragma unroll
            for (int nt = 0; nt < 4; nt++) {
                int b = bn + wn * 32 + nt * 8 + c * 2;
                float x0 = x[(size_t)b * VV + v];
                float x1 = x[(size_t)(b + 1) * VV + v];
                float d0 = fmaxf(acc[mt][nt][half * 2 + 0], EPSF);
                float d1 = fmaxf(acc[mt][nt][half * 2 + 1], EPSF);
                float2 o = {__uint_as_float(to_tf32(x0 / d0)),
                            __uint_as_float(to_tf32(x1 / d1))};
                *(float2*)&ratio[v * BSZ + b] = o;
            }
        }
}

// GEMM2: W = phi * (ratio@thR^T); S colsum.  N-tile = 64 k-columns.
__global__ __launch_bounds__(256, 3) void wszs_gemm_tc(
    const float* __restrict__ ratio, const float* __restrict__ thR,
    const float* __restrict__ phi, float* __restrict__ W, float* __restrict__ S) {
    extern __shared__ uint32_t dsm[];
    __shared__ float sS[128];
    const int bn = blockIdx.x * 64;      // k-column offset
    const int bv = blockIdx.y * 128;
    const int tid = threadIdx.x;
    const int wid = tid >> 5, lane = tid & 31;
    const int wm = wid >> 1, wn = wid & 1;
    const int g = lane >> 2, c = lane & 3;
    float acc[2][4][4] = {};

    auto loadT = [&](int kk, int buf) {
        uint32_t* As = dsm + buf * G2_STAGE;
        uint32_t* Bs = As + G2_ASZ;
#pragma unroll
        for (int e = 0; e < 4; e++) {            // A: ratio 128 rows x 32
            int idx = tid + e * 256;
            int m = idx >> 3, c4 = idx & 7;
            bool v = (bv + m) < VV;
            const float* src = v ? &ratio[(size_t)(bv + m) * BSZ + kk + c4 * 4] : ratio;
            cpa16(&As[m * 36 + c4 * 4], src, v);
        }
#pragma unroll
        for (int e = 0; e < 2; e++) {            // B: thR 64 n-rows x 32
            int idx = tid + e * 256;
            int n = idx >> 3, c4 = idx & 7;
            cpa16(&Bs[n * 36 + c4 * 4], &thR[(bn + n) * BSZ + kk + c4 * 4], true);
        }
        CP_COMMIT();
    };

    loadT(0, 0);
    for (int kt = 0; kt < 16; kt++) {
        int cur = kt & 1;
        if (kt < 15) { loadT((kt + 1) * 32, cur ^ 1); CP_WAIT1(); }
        else         { CP_WAIT0(); }
        __syncthreads();
        uint32_t* As = dsm + cur * G2_STAGE;
        kt_mk_nk64(As, As + G2_ASZ, wm, wn, g, c, acc);
        __syncthreads();
    }
    if (tid < 128) sS[tid] = 0.f;
    __syncthreads();
    float colp[4][2] = {};
#pragma unroll
    for (int mt = 0; mt < 2; mt++)
#pragma unroll
        for (int half = 0; half < 2; half++) {
            int v = bv + wm * 32 + mt * 16 + g + half * 8;
            if (v >= VV) continue;
#pragma unroll
            for (int nt = 0; nt < 4; nt++) {
                int k = bn + wn * 32 + nt * 8 + c * 2;
                float2 ph = *(const float2*)&phi[v * 128 + k];
                float w0 = ph.x * acc[mt][nt][half * 2 + 0];
                float w1 = ph.y * acc[mt][nt][half * 2 + 1];
                float2 o = {w0, w1};
                *(float2*)&W[v * 128 + k] = o;
                colp[nt][0] += w0;
                colp[nt][1] += w1;
            }
        }
#pragma unroll
    for (int nt = 0; nt < 4; nt++) {
        int k = bn + wn * 32 + nt * 8 + c * 2;
        atomicAdd(&sS[k], colp[nt][0]);
        atomicAdd(&sS[k + 1], colp[nt][1]);
    }
    __syncthreads();
    if (tid < 128) atomicAdd(&S[tid], sS[tid]);
}

// GEMM3 (split-K over v): part[z][k][b], N-tile = 64 b-columns
__global__ __launch_bounds__(256, 3) void xnext_gemm_tc(
    int chunk,
    const float* __restrict__ phiR, const float* __restrict__ ratio,
    float* __restrict__ part) {
    extern __shared__ uint32_t dsm[];
    const int bn = blockIdx.x * 64;
    const int z = blockIdx.z;
    const int v0 = z * chunk;
    const int vend = min(v0 + chunk, VV);
    const int NT = (vend - v0 + 31) / 32;
    const int tid = threadIdx.x;
    const int wid = tid >> 5, lane = tid & 31;
    const int wm = wid >> 1, wn = wid & 1;
    const int g = lane >> 2, c = lane & 3;
    float acc[2][4][4] = {};

    auto loadT = [&](int vv, int buf) {
        uint32_t* As = dsm + buf * G3_STAGE;
        uint32_t* Bs = As + G3_ASZ;
#pragma unroll
        for (int e = 0; e < 4; e++) {            // A: phi 32 v-rows x 128
            int idx = tid + e * 256;
            int vi = idx >> 5, c4 = idx & 31;
            bool va = (vv + vi) < vend;
            const float* srcA = va ? &phiR[(size_t)(vv + vi) * 128 + c4 * 4] : phiR;
            cpa16(&As[vi * 132 + c4 * 4], srcA, va);
        }
#pragma unroll
        for (int e = 0; e < 2; e++) {            // B: ratio 32 v-rows x 64
            int idx = tid + e * 256;
            int vi = idx >> 4, c4 = idx & 15;
            bool vb = (vv + vi) < vend;
            const float* srcB = vb ? &ratio[(size_t)(vv + vi) * BSZ + bn + c4 * 4] : ratio;
            cpa16(&Bs[vi * 68 + c4 * 4], srcB, vb);
        }
        CP_COMMIT();
    };

    loadT(v0, 0);
    for (int kt = 0; kt < NT; kt++) {
        int cur = kt & 1;
        if (kt < NT - 1) { loadT(v0 + (kt + 1) * 32, cur ^ 1); CP_WAIT1(); }
        else             { CP_WAIT0(); }
        __syncthreads();
        uint32_t* As = dsm + cur * G3_STAGE;
        kt_km_kn64(As, As + G3_ASZ, wm, wn, g, c, acc);
        __syncthreads();
    }
#pragma unroll
    for (int mt = 0; mt < 2; mt++)
#pragma unroll
        for (int half = 0; half < 2; half++) {
            int k = wm * 32 + mt * 16 + g + half * 8;
#pragma unroll
            for (int nt = 0; nt < 4; nt++) {
                int b = bn + wn * 32 + nt * 8 + c * 2;
                float2 o = {acc[mt][nt][half * 2 + 0], acc[mt][nt][half * 2 + 1]};
                *(float2*)&part[((long)z * 128 + k) * BSZ + b] = o;
            }
        }
}

// ============================================================================
// Fused step+norm persistent kernel (layer 0): 148 blocks, own barrier
// ============================================================================
__device__ __forceinline__ void gbar2() {
    __threadfence();
    __syncthreads();
    if (threadIdx.x == 0) {
        unsigned g = *(volatile unsigned*)&g_bargen2;
        if (atomicAdd(&g_barcnt2, 1u) == NSN - 1) {
            g_barcnt2 = 0u;
            __threadfence();
            atomicAdd(&g_bargen2, 1u);
        } else {
            while (*(volatile unsigned*)&g_bargen2 == g) { __nanosleep(40); }
        }
    }
    __syncthreads();
}

__global__ __launch_bounds__(256) void step_norm_kernel(
    float* __restrict__ W,
    const float* __restrict__ phi, const float* __restrict__ noise,
    const float* __restrict__ S, const float* __restrict__ phisum,
    const float* __restrict__ qsum, float* __restrict__ P,
    float* __restrict__ out) {
    __shared__ float sP[128];
    const int tid = threadIdx.x;
    const int T = blockIdx.x * 256 + tid;
    const int STR = NSN * 256;
    const int DK = VV * K0;
    const int k = T & 127;

    float s = S[k];
    float inv_n = 1.f / fmaxf(MBR * s, EPSF);
    float tmpsum = MBR * s + 0.1f * (float)VV;
    float c2 = sqrtf(2.f * inv_n);
    float ps = phisum[k];
    float Tt = ps + inv_n * (tmpsum - tmpsum * ps) + c2 * qsum[k];
    float a = Tt - 1.f;

    if (tid < 128) sP[tid] = 0.f;
    __syncthreads();
    float acc = 0.f;
    for (int i = T; i < DK; i += STR) {
        float w = W[i], ph = phi[i], nz = noise[i];
        float st = ph + inv_n * (MBR * w + 0.1f - tmpsum * ph) + c2 * sqrtf(ph) * nz;
        float p = fmaxf(EPSF, st - a * ph);
        W[i] = p;
        acc += p;
    }
    atomicAdd(&sP[k], acc);
    __syncthreads();
    if (tid < 128) atomicAdd(&P[tid], sP[tid]);
    gbar2();

    float inv = 1.f / fmaxf(EPSF, P[k]);
    for (int i = T; i < DK; i += STR)
        out[i] = W[i] * inv;
}

// ============================================================================
// Fused persistent kernel: split-K reduce + layers 1-2 (NBF blocks)
// ============================================================================
__device__ __forceinline__ void gbar() {
    __threadfence();
    __syncthreads();
    if (threadIdx.x == 0) {
        unsigned g = *(volatile unsigned*)&g_bargen;
        if (atomicAdd(&g_barcnt, 1u) == NBF - 1) {
            g_barcnt = 0u;
            __threadfence();
            atomicAdd(&g_bargen, 1u);
        } else {
            while (*(volatile unsigned*)&g_bargen == g) { __nanosleep(60); }
        }
    }
    __syncthreads();
}

__device__ void small_layer(int D, int K,
                            const float* __restrict__ phi,
                            const float* __restrict__ theta,
                            const float* __restrict__ noise,
                            const float* __restrict__ xin,
                            float* __restrict__ ratio, float* __restrict__ Wb,
                            float* __restrict__ S, float* __restrict__ P,
                            const float* __restrict__ phisum,
                            const float* __restrict__ qsum,
                            float* __restrict__ out, float* __restrict__ xout) {
    const int T = blockIdx.x * NTF + threadIdx.x;
    const int DB = D * BSZ, DK = D * K;

    for (int i = T; i < DB; i += NTOT) {
        int v = i >> 9, b = i & 511;
        float s = 0.f;
        for (int k = 0; k < K; k++) s += phi[v * K + k] * theta[k * BSZ + b];
        float d = fmaxf(s, EPSF);
        float xv = xin[i];
        ratio[i] = digammaf_(d + xv) - digammaf_(d);
    }
    gbar();

    for (int i = T; i < DK; i += NTOT) {
        int v = i / K, k = i - v * K;
        const float* rp = ratio + v * BSZ;
        const float* tp = theta + k * BSZ;
        float s = 0.f;
        for (int b = 0; b < BSZ; b += 4) {
            float4 r4 = *(const float4*)&rp[b];
            float4 t4 = *(const float4*)&tp[b];
            s += r4.x * t4.x + r4.y * t4.y + r4.z * t4.z + r4.w * t4.w;
        }
        float w = phi[i] * s;
        Wb[i] = w;
        atomicAdd(&S[k], w);
    }
    gbar();

    for (int i = T; i < DK; i += NTOT) {
        int k = i % K;
        float s = S[k];
        float inv_n = 1.f / fmaxf(MBR * s, EPSF);
        float tmpsum = MBR * s + 0.1f * (float)D;
        float c2 = sqrtf(2.f * inv_n);
        float psum = phisum[k];
        float Tt = psum + inv_n * (tmpsum - tmpsum * psum) + c2 * qsum[k];
        float a = Tt - 1.f;
        float w = Wb[i], ph = phi[i], nz = noise[i];
        float st = ph + inv_n * (MBR * w + 0.1f - tmpsum * ph) + c2 * sqrtf(ph) * nz;
        float p = fmaxf(EPSF, st - a * ph);
        Wb[i] = p;
        atomicAdd(&P[k], p);
    }
    gbar();

    for (int i = T; i < DK; i += NTOT) {
        int k = i % K;
        out[i] = Wb[i] / fmaxf(EPSF, P[k]);
    }

    if (xout) {
        for (int i = T; i < K * BSZ; i += NTOT) {
            int k = i >> 9, b = i & 511;
            float s = 0.f;
            for (int v = 0; v < D; v++)
                s += phi[v * K + k] * ratio[v * BSZ + b];
            xout[i] = theta[i] * s;
        }
        gbar();
    }
}

__global__ __launch_bounds__(NTF) void fused_small_kernel(
    const float* __restrict__ part, const float* __restrict__ th0,
    const float* __restrict__ phi1, const float* __restrict__ th1,
    const float* __restrict__ nz1,
    const float* __restrict__ phi2, const float* __restrict__ th2,
    const float* __restrict__ nz2,
    float* __restrict__ xa,
    float* __restrict__ ratio1, float* __restrict__ ratio2,
    float* __restrict__ W1, float* __restrict__ W2, float* __restrict__ xb,
    float* __restrict__ S, float* __restrict__ P,
    const float* __restrict__ phisum, const float* __restrict__ qsum,
    float* __restrict__ out1, float* __restrict__ out2) {
    const int T = blockIdx.x * NTF + threadIdx.x;
    const int n = K0 * BSZ;
    for (int i = T; i < n; i += NTOT) {
        float s = 0.f;
        for (int z = 0; z < NZ0; z++) s += part[z * n + i];
        xa[i] = th0[i] * s;
    }
    gbar();
    small_layer(128, 64, phi1, th1, nz1, xa, ratio1, W1,
                S + 128, P + 128, phisum + 128, qsum + 128, out1, xb);
    small_layer(64, 32, phi2, th2, nz2, xb, ratio2, W2,
                S + 256, P + 256, phisum + 256, qsum + 256, out2, nullptr);
}

// ---------------- host orchestration ----------------
extern "C" void kernel_launch(void* const* d_in, const int* in_sizes, int n_in,
                              void* d_out, int out_size) {
    const float* x      = (const float*)d_in[0];
    const float* theta0 = (const float*)d_in[1];
    const float* theta1 = (const float*)d_in[2];
    const float* theta2 = (const float*)d_in[3];
    const float* phi0   = (const float*)d_in[4];
    const float* phi1   = (const float*)d_in[5];
    const float* phi2   = (const float*)d_in[6];
    const float* noise0 = (const float*)d_in[7];
    const float* noise1 = (const float*)d_in[8];
    const float* noise2 = (const float*)d_in[9];
    float* out = (float*)d_out;

    float *ratio, *phiR, *thR, *W, *part, *xa, *xb;
    float *ratio1, *ratio2, *W1, *W2, *S, *P, *phisum, *qsum;
    cudaGetSymbolAddress((void**)&ratio, g_ratio);
    cudaGetSymbolAddress((void**)&phiR, g_phiR);
    cudaGetSymbolAddress((void**)&thR, g_thR);
    cudaGetSymbolAddress((void**)&W, g_W);
    cudaGetSymbolAddress((void**)&part, g_part);
    cudaGetSymbolAddress((void**)&xa, g_xa);
    cudaGetSymbolAddress((void**)&xb, g_xb);
    cudaGetSymbolAddress((void**)&ratio1, g_ratio1);
    cudaGetSymbolAddress((void**)&ratio2, g_ratio2);
    cudaGetSymbolAddress((void**)&W1, g_W1);
    cudaGetSymbolAddress((void**)&W2, g_W2);
    cudaGetSymbolAddress((void**)&S, g_S);
    cudaGetSymbolAddress((void**)&P, g_P);
    cudaGetSymbolAddress((void**)&phisum, g_phisum);
    cudaGetSymbolAddress((void**)&qsum, g_qsum);

    static cudaStream_t s1 = nullptr, s2 = nullptr;
    static cudaEvent_t ev0, evPre, evCs, evG1, evJ;
    if (!s1) {
        cudaStreamCreateWithFlags(&s1, cudaStreamNonBlocking);
        cudaStreamCreateWithFlags(&s2, cudaStreamNonBlocking);
        cudaEventCreateWithFlags(&ev0, cudaEventDisableTiming);
        cudaEventCreateWithFlags(&evPre, cudaEventDisableTiming);
        cudaEventCreateWithFlags(&evCs, cudaEventDisableTiming);
        cudaEventCreateWithFlags(&evG1, cudaEventDisableTiming);
        cudaEventCreateWithFlags(&evJ, cudaEventDisableTiming);
        cudaFuncSetAttribute(ratio_gemm_tc, cudaFuncAttributeMaxDynamicSharedMemorySize,
                             2 * G1_STAGE * 4);
        cudaFuncSetAttribute(wszs_gemm_tc, cudaFuncAttributeMaxDynamicSharedMemorySize,
                             2 * G2_STAGE * 4);
        cudaFuncSetAttribute(xnext_gemm_tc, cudaFuncAttributeMaxDynamicSharedMemorySize,
                             2 * G3_STAGE * 4);
    }

    // ---- fork: zero accumulators first ----
    zero384_kernel<<<1, 384>>>(S, P, phisum, qsum);
    cudaEventRecord(ev0, 0);
    cudaStreamWaitEvent(s1, ev0, 0);
    cudaStreamWaitEvent(s2, ev0, 0);

    // s1: colstats
    colstats3_kernel<<<941, 256, 0, s1>>>(phi0, noise0, phi1, noise1, phi2, noise2,
                                          phisum, qsum);
    cudaEventRecord(evCs, s1);

    // s2: preround
    int n4a = VV * 128 / 4, n4b = 128 * BSZ / 4;
    preround_kernel<<<(n4a + n4b + 255) / 256, 256, 0, s2>>>(
        phi0, (uint32_t*)phiR, n4a, theta0, (uint32_t*)thR, n4b);
    cudaEventRecord(evPre, s2);

    // main: GEMM1
    cudaStreamWaitEvent(0, evPre, 0);
    ratio_gemm_tc<<<dim3(BSZ / 64, (VV + 127) / 128), 256, 2 * G1_STAGE * 4>>>(
        phiR, thR, x, ratio);
    cudaEventRecord(evG1, 0);

    // ---- branch B on s1: GEMM3 -> fused(reduce + small layers) ----
    cudaStreamWaitEvent(s1, evG1, 0);
    int chunk = (VV + NZ0 - 1) / NZ0;
    xnext_gemm_tc<<<dim3(BSZ / 64, 1, NZ0), 256, 2 * G3_STAGE * 4, s1>>>(
        chunk, phiR, ratio, part);
    fused_small_kernel<<<NBF, NTF, 0, s1>>>(
        part, theta0, phi1, theta1, noise1, phi2, theta2, noise2, xa,
        ratio1, ratio2, W1, W2, xb, S, P, phisum, qsum,
        out + VV * 128, out + VV * 128 + 128 * 64);
    cudaEventRecord(evJ, s1);

    // ---- branch A on main: GEMM2 -> fused step+norm ----
    wszs_gemm_tc<<<dim3(2, (VV + 127) / 128), 256, 2 * G2_STAGE * 4>>>(
        ratio, thR, phi0, W, S);
    cudaStreamWaitEvent(0, evCs, 0);
    step_norm_kernel<<<NSN, 256>>>(W, phi0, noise0, S, phisum, qsum, P, out);

    // ---- join ----
    cudaStreamWaitEvent(0, evJ, 0);
}

// round 16
// speedup vs baseline: 1.1589x; 1.1589x over previous
#include <cuda_runtime.h>
#include <cstdint>

#define BSZ 512
#define VV  30000
#define K0  128
#define EPSF 2.2e-10f
#define MBR 100.0f
#define NZ0 37
#define NBF 48
#define NTF 256
#define NTOT (NBF * NTF)
#define NSN 148

// ---------------- scratch (device globals: allocation-free) ----------------
__device__ float g_ratio[VV * BSZ];
__device__ float g_phiR[VV * K0];
__device__ float g_thR[K0 * BSZ];
__device__ float g_W[VV * K0];
__device__ float g_part[NZ0 * K0 * BSZ];
__device__ float g_xa[K0 * BSZ];
__device__ float g_xb[K0 * BSZ];
__device__ float g_ratio1[K0 * BSZ];
__device__ float g_ratio2[64 * BSZ];
__device__ float g_W1[K0 * 64];
__device__ float g_W2[64 * 32];
__device__ float g_S[384];
__device__ float g_P[384];
__device__ float g_phisum[384];
__device__ float g_qsum[384];
__device__ unsigned g_barcnt;
__device__ unsigned g_bargen;
__device__ unsigned g_barcnt2;
__device__ unsigned g_bargen2;

// ---------------- digamma (fast) ----------------
__device__ __forceinline__ float digammaf_(float x) {
    float r = 0.f;
    while (x < 6.f) { r -= __fdividef(1.f, x); x += 1.f; }
    float inv  = __fdividef(1.f, x);
    float inv2 = inv * inv;
    float ser  = inv2 * (0.08333333333f - inv2 * (0.008333333333f - inv2 * 0.003968253968f));
    return r + logf(x) - 0.5f * inv - ser;
}

// ---------------- tf32 + mma + cp.async helpers ----------------
__device__ __forceinline__ uint32_t to_tf32(float x) {
    uint32_t r;
    asm("cvt.rna.tf32.f32 %0, %1;" : "=r"(r) : "f"(x));
    return r;
}

__device__ __forceinline__ void mma8(float* d,
                                     uint32_t a0, uint32_t a1, uint32_t a2, uint32_t a3,
                                     uint32_t b0, uint32_t b1) {
    asm volatile(
        "mma.sync.aligned.m16n8k8.row.col.f32.tf32.tf32.f32 "
        "{%0,%1,%2,%3},{%4,%5,%6,%7},{%8,%9},{%0,%1,%2,%3};\n"
        : "+f"(d[0]), "+f"(d[1]), "+f"(d[2]), "+f"(d[3])
        : "r"(a0), "r"(a1), "r"(a2), "r"(a3), "r"(b0), "r"(b1));
}

__device__ __forceinline__ void cpa16(uint32_t* s, const void* gsrc, bool v) {
    uint32_t sa = (uint32_t)__cvta_generic_to_shared(s);
    int sz = v ? 16 : 0;
    asm volatile("cp.async.cg.shared.global [%0], [%1], 16, %2;\n"
                 :: "r"(sa), "l"(gsrc), "r"(sz) : "memory");
}
#define CP_COMMIT() asm volatile("cp.async.commit_group;\n" ::: "memory")
#define CP_WAIT1()  asm volatile("cp.async.wait_group 1;\n" ::: "memory")
#define CP_WAIT0()  asm volatile("cp.async.wait_group 0;\n" ::: "memory")

// ---- GEMM1 k-tile (128x64, acc[2][4][4]): A [m][k] s36, B [k][n] s68 ----
__device__ __forceinline__ void kt_mk_kn64(
    const uint32_t* __restrict__ As, const uint32_t* __restrict__ Bs,
    int wm, int wn, int g, int c, float acc[2][4][4]) {
#pragma unroll
    for (int k8 = 0; k8 < 4; k8++) {
        const int k0 = k8 * 8;
        uint32_t a[2][4];
#pragma unroll
        for (int mt = 0; mt < 2; mt++) {
            int r = wm * 32 + mt * 16 + g;
            a[mt][0] = As[r * 36 + k0 + c];
            a[mt][1] = As[(r + 8) * 36 + k0 + c];
            a[mt][2] = As[r * 36 + k0 + c + 4];
            a[mt][3] = As[(r + 8) * 36 + k0 + c + 4];
        }
#pragma unroll
        for (int nt = 0; nt < 4; nt++) {
            int n = wn * 32 + nt * 8 + g;
            uint32_t b0 = Bs[(k0 + c) * 68 + n];
            uint32_t b1 = Bs[(k0 + c + 4) * 68 + n];
#pragma unroll
            for (int mt = 0; mt < 2; mt++)
                mma8(acc[mt][nt], a[mt][0], a[mt][1], a[mt][2], a[mt][3], b0, b1);
        }
    }
}
// ---- 128x128 k-tiles (acc[2][8][4]) for GEMM2/GEMM3 ----
__device__ __forceinline__ void ktile32_mk_nk(
    const uint32_t* __restrict__ As, const uint32_t* __restrict__ Bs,
    int wm, int wn, int g, int c, float acc[2][8][4]) {
#pragma unroll
    for (int k8 = 0; k8 < 4; k8++) {
        const int k0 = k8 * 8;
        uint32_t a[2][4];
#pragma unroll
        for (int mt = 0; mt < 2; mt++) {
            int r = wm * 32 + mt * 16 + g;
            a[mt][0] = As[r * 36 + k0 + c];
            a[mt][1] = As[(r + 8) * 36 + k0 + c];
            a[mt][2] = As[r * 36 + k0 + c + 4];
            a[mt][3] = As[(r + 8) * 36 + k0 + c + 4];
        }
#pragma unroll
        for (int nt = 0; nt < 8; nt++) {
            int n = wn * 64 + nt * 8 + g;
            uint32_t b0 = Bs[n * 36 + k0 + c];
            uint32_t b1 = Bs[n * 36 + k0 + c + 4];
#pragma unroll
            for (int mt = 0; mt < 2; mt++)
                mma8(acc[mt][nt], a[mt][0], a[mt][1], a[mt][2], a[mt][3], b0, b1);
        }
    }
}
__device__ __forceinline__ void ktile32_km_kn(
    const uint32_t* __restrict__ As, const uint32_t* __restrict__ Bs,
    int wm, int wn, int g, int c, float acc[2][8][4]) {
#pragma unroll
    for (int k8 = 0; k8 < 4; k8++) {
        const int k0 = k8 * 8;
        uint32_t a[2][4];
#pragma unroll
        for (int mt = 0; mt < 2; mt++) {
            int r = wm * 32 + mt * 16 + g;
            a[mt][0] = As[(k0 + c) * 132 + r];
            a[mt][1] = As[(k0 + c) * 132 + r + 8];
            a[mt][2] = As[(k0 + c + 4) * 132 + r];
            a[mt][3] = As[(k0 + c + 4) * 132 + r + 8];
        }
#pragma unroll
        for (int nt = 0; nt < 8; nt++) {
            int n = wn * 64 + nt * 8 + g;
            uint32_t b0 = Bs[(k0 + c) * 132 + n];
            uint32_t b1 = Bs[(k0 + c + 4) * 132 + n];
#pragma unroll
            for (int mt = 0; mt < 2; mt++)
                mma8(acc[mt][nt], a[mt][0], a[mt][1], a[mt][2], a[mt][3], b0, b1);
        }
    }
}

// ---------------- zero all slot accumulators ----------------
__global__ void zero384_kernel(float* S, float* P, float* PS, float* QS) {
    int i = threadIdx.x;
    S[i] = 0.f; P[i] = 0.f; PS[i] = 0.f; QS[i] = 0.f;
}

// ---------------- combined colstats for 3 layers ----------------
__global__ void colstats3_kernel(
    const float* __restrict__ p0, const float* __restrict__ n0,
    const float* __restrict__ p1, const float* __restrict__ n1,
    const float* __restrict__ p2, const float* __restrict__ n2,
    float* __restrict__ phisum, float* __restrict__ qsum) {
    int b = blockIdx.x;
    const float *phi, *noise; int DK, K, base; float *ps, *qs;
    if (b < 938)      { phi = p0; noise = n0; DK = VV * 128; K = 128; base = b * 4096;        ps = phisum;       qs = qsum; }
    else if (b < 940) { phi = p1; noise = n1; DK = 128 * 64; K = 64;  base = (b - 938) * 4096; ps = phisum + 128; qs = qsum + 128; }
    else              { phi = p2; noise = n2; DK = 64 * 32;  K = 32;  base = 0;               ps = phisum + 256; qs = qsum + 256; }
    __shared__ float sA[128], sB[128];
    int tid = threadIdx.x;
    if (tid < K) { sA[tid] = 0.f; sB[tid] = 0.f; }
    __syncthreads();
    int k = (base + tid) & (K - 1);
    float pa = 0.f, pb = 0.f;
#pragma unroll 4
    for (int e = 0; e < 16; e++) {
        int idx = base + e * 256 + tid;
        if (idx < DK) {
            float ph = phi[idx], nz = noise[idx];
            pa += ph;
            pb += sqrtf(ph) * nz;
        }
    }
    atomicAdd(&sA[k], pa);
    atomicAdd(&sB[k], pb);
    __syncthreads();
    if (tid < K) { atomicAdd(&ps[tid], sA[tid]); atomicAdd(&qs[tid], sB[tid]); }
}

// ---------------- pre-round phi0/theta0 to tf32 ----------------
__global__ void preround_kernel(const float* __restrict__ a, uint32_t* __restrict__ oa, int n4a,
                                const float* __restrict__ b, uint32_t* __restrict__ ob, int n4b) {
    int i = blockIdx.x * 256 + threadIdx.x;
    if (i < n4a) {
        float4 v = ((const float4*)a)[i];
        uint4 o = {to_tf32(v.x), to_tf32(v.y), to_tf32(v.z), to_tf32(v.w)};
        ((uint4*)oa)[i] = o;
    } else if (i < n4a + n4b) {
        int j = i - n4a;
        float4 v = ((const float4*)b)[j];
        uint4 o = {to_tf32(v.x), to_tf32(v.y), to_tf32(v.z), to_tf32(v.w)};
        ((uint4*)ob)[j] = o;
    }
}

// ============================================================================
// GEMM1: 128x64 tile, 2-stage, 3 CTAs/SM (R15 winner)
// ============================================================================
#define G1_ASZ (128 * 36)
#define G1_BSZ (32 * 68)
#define G1_STAGE (G1_ASZ + G1_BSZ)
// GEMM2/3: 128x128 tile, 3-stage, 2 CTAs/SM (R14 winner)
#define G2_ASZ (128 * 36)
#define G2_STAGE (2 * G2_ASZ)
#define G3_ASZ (32 * 132)
#define G3_STAGE (2 * G3_ASZ)

__global__ __launch_bounds__(256, 3) void ratio_gemm_tc(
    const float* __restrict__ phiR, const float* __restrict__ thR,
    const float* __restrict__ x, float* __restrict__ ratio) {
    extern __shared__ uint32_t dsm[];
    const int bn = blockIdx.x * 64, bv = blockIdx.y * 128;
    const int tid = threadIdx.x;
    const int wid = tid >> 5, lane = tid & 31;
    const int wm = wid >> 1, wn = wid & 1;
    const int g = lane >> 2, c = lane & 3;
    float acc[2][4][4] = {};

    auto loadT = [&](int kk, int buf) {
        uint32_t* As = dsm + buf * G1_STAGE;
        uint32_t* Bs = As + G1_ASZ;
#pragma unroll
        for (int e = 0; e < 4; e++) {
            int idx = tid + e * 256;
            int m = idx >> 3, c4 = idx & 7;
            bool v = (bv + m) < VV;
            const float* src = v ? &phiR[(size_t)(bv + m) * 128 + kk + c4 * 4] : phiR;
            cpa16(&As[m * 36 + c4 * 4], src, v);
        }
#pragma unroll
        for (int e = 0; e < 2; e++) {
            int idx = tid + e * 256;
            int r = idx >> 4, c4 = idx & 15;
            cpa16(&Bs[r * 68 + c4 * 4], &thR[(kk + r) * BSZ + bn + c4 * 4], true);
        }
        CP_COMMIT();
    };

    loadT(0, 0);
#pragma unroll
    for (int kt = 0; kt < 4; kt++) {
        int cur = kt & 1;
        if (kt < 3) { loadT((kt + 1) * 32, cur ^ 1); CP_WAIT1(); }
        else        { CP_WAIT0(); }
        __syncthreads();
        uint32_t* As = dsm + cur * G1_STAGE;
        kt_mk_kn64(As, As + G1_ASZ, wm, wn, g, c, acc);
        __syncthreads();
    }
#pragma unroll
    for (int mt = 0; mt < 2; mt++)
#pragma unroll
        for (int half = 0; half < 2; half++) {
            int v = bv + wm * 32 + mt * 16 + g + half * 8;
            if (v >= VV) continue;
#pragma unroll
            for (int nt = 0; nt < 4; nt++) {
                int b = bn + wn * 32 + nt * 8 + c * 2;
                float x0 = x[(size_t)b * VV + v];
                float x1 = x[(size_t)(b + 1) * VV + v];
                float d0 = fmaxf(acc[mt][nt][half * 2 + 0], EPSF);
                float d1 = fmaxf(acc[mt][nt][half * 2 + 1], EPSF);
                float2 o = {__uint_as_float(to_tf32(x0 / d0)),
                            __uint_as_float(to_tf32(x1 / d1))};
                *(float2*)&ratio[v * BSZ + b] = o;
            }
        }
}

__global__ __launch_bounds__(256, 2) void wszs_gemm_tc(
    const float* __restrict__ ratio, const float* __restrict__ thR,
    const float* __restrict__ phi, float* __restrict__ W, float* __restrict__ S) {
    extern __shared__ uint32_t dsm[];
    __shared__ float sS[128];
    const int bv = blockIdx.y * 128;
    const int tid = threadIdx.x;
    const int wid = tid >> 5, lane = tid & 31;
    const int wm = wid >> 1, wn = wid & 1;
    const int g = lane >> 2, c = lane & 3;
    float acc[2][8][4] = {};

    auto loadT = [&](int kk, int buf) {
        uint32_t* As = dsm + buf * G2_STAGE;
        uint32_t* Bs = As + G2_ASZ;
#pragma unroll
        for (int e = 0; e < 4; e++) {
            int idx = tid + e * 256;
            int m = idx >> 3, c4 = idx & 7;
            bool v = (bv + m) < VV;
            const float* src = v ? &ratio[(size_t)(bv + m) * BSZ + kk + c4 * 4] : ratio;
            cpa16(&As[m * 36 + c4 * 4], src, v);
        }
#pragma unroll
        for (int e = 0; e < 4; e++) {
            int idx = tid + e * 256;
            int n = idx >> 3, c4 = idx & 7;
            cpa16(&Bs[n * 36 + c4 * 4], &thR[n * BSZ + kk + c4 * 4], true);
        }
        CP_COMMIT();
    };

    loadT(0, 0);
    loadT(32, 1);
    for (int kt = 0; kt < 16; kt++) {
        CP_WAIT1();
        __syncthreads();
        if (kt + 2 < 16) loadT((kt + 2) * 32, (kt + 2) % 3);
        uint32_t* As = dsm + (kt % 3) * G2_STAGE;
        ktile32_mk_nk(As, As + G2_ASZ, wm, wn, g, c, acc);
    }
    __syncthreads();
    if (tid < 128) sS[tid] = 0.f;
    __syncthreads();
    float colp[8][2] = {};
#pragma unroll
    for (int mt = 0; mt < 2; mt++)
#pragma unroll
        for (int half = 0; half < 2; half++) {
            int v = bv + wm * 32 + mt * 16 + g + half * 8;
            if (v >= VV) continue;
#pragma unroll
            for (int nt = 0; nt < 8; nt++) {
                int k = wn * 64 + nt * 8 + c * 2;
                float2 ph = *(const float2*)&phi[v * 128 + k];
                float w0 = ph.x * acc[mt][nt][half * 2 + 0];
                float w1 = ph.y * acc[mt][nt][half * 2 + 1];
                float2 o = {w0, w1};
                *(float2*)&W[v * 128 + k] = o;
                colp[nt][0] += w0;
                colp[nt][1] += w1;
            }
        }
#pragma unroll
    for (int nt = 0; nt < 8; nt++) {
        int k = wn * 64 + nt * 8 + c * 2;
        atomicAdd(&sS[k], colp[nt][0]);
        atomicAdd(&sS[k + 1], colp[nt][1]);
    }
    __syncthreads();
    if (tid < 128) atomicAdd(&S[tid], sS[tid]);
}

__global__ __launch_bounds__(256, 2) void xnext_gemm_tc(
    int chunk,
    const float* __restrict__ phiR, const float* __restrict__ ratio,
    float* __restrict__ part) {
    extern __shared__ uint32_t dsm[];
    const int bn = blockIdx.x * 128;
    const int z = blockIdx.z;
    const int v0 = z * chunk;
    const int vend = min(v0 + chunk, VV);
    const int NT = (vend - v0 + 31) / 32;
    const int tid = threadIdx.x;
    const int wid = tid >> 5, lane = tid & 31;
    const int wm = wid >> 1, wn = wid & 1;
    const int g = lane >> 2, c = lane & 3;
    float acc[2][8][4] = {};

    auto loadT = [&](int vv, int buf) {
        uint32_t* As = dsm + buf * G3_STAGE;
        uint32_t* Bs = As + G3_ASZ;
#pragma unroll
        for (int e = 0; e < 4; e++) {
            int idx = tid + e * 256;
            int vi = idx >> 5, c4 = idx & 31;
            bool va = (vv + vi) < vend;
            const float* srcA = va ? &phiR[(size_t)(vv + vi) * 128 + c4 * 4] : phiR;
            cpa16(&As[vi * 132 + c4 * 4], srcA, va);
            const float* srcB = va ? &ratio[(size_t)(vv + vi) * BSZ + bn + c4 * 4] : ratio;
            cpa16(&Bs[vi * 132 + c4 * 4], srcB, va);
        }
        CP_COMMIT();
    };

    loadT(v0, 0);
    if (NT > 1) loadT(v0 + 32, 1);
    for (int kt = 0; kt < NT; kt++) {
        if (kt + 1 < NT) CP_WAIT1(); else CP_WAIT0();
        __syncthreads();
        if (kt + 2 < NT) loadT(v0 + (kt + 2) * 32, (kt + 2) % 3);
        uint32_t* As = dsm + (kt % 3) * G3_STAGE;
        ktile32_km_kn(As, As + G3_ASZ, wm, wn, g, c, acc);
    }
#pragma unroll
    for (int mt = 0; mt < 2; mt++)
#pragma unroll
        for (int half = 0; half < 2; half++) {
            int k = wm * 32 + mt * 16 + g + half * 8;
#pragma unroll
            for (int nt = 0; nt < 8; nt++) {
                int b = bn + wn * 64 + nt * 8 + c * 2;
                float2 o = {acc[mt][nt][half * 2 + 0], acc[mt][nt][half * 2 + 1]};
                *(float2*)&part[((long)z * 128 + k) * BSZ + b] = o;
            }
        }
}

// ============================================================================
// Fused step+norm persistent kernel (layer 0)
// ============================================================================
__device__ __forceinline__ void gbar2() {
    __threadfence();
    __syncthreads();
    if (threadIdx.x == 0) {
        unsigned g = *(volatile unsigned*)&g_bargen2;
        if (atomicAdd(&g_barcnt2, 1u) == NSN - 1) {
            g_barcnt2 = 0u;
            __threadfence();
            atomicAdd(&g_bargen2, 1u);
        } else {
            while (*(volatile unsigned*)&g_bargen2 == g) { __nanosleep(40); }
        }
    }
    __syncthreads();
}

__global__ __launch_bounds__(256) void step_norm_kernel(
    float* __restrict__ W,
    const float* __restrict__ phi, const float* __restrict__ noise,
    const float* __restrict__ S, const float* __restrict__ phisum,
    const float* __restrict__ qsum, float* __restrict__ P,
    float* __restrict__ out) {
    __shared__ float sP[128];
    const int tid = threadIdx.x;
    const int T = blockIdx.x * 256 + tid;
    const int STR = NSN * 256;
    const int DK = VV * K0;
    const int k = T & 127;

    float s = S[k];
    float inv_n = 1.f / fmaxf(MBR * s, EPSF);
    float tmpsum = MBR * s + 0.1f * (float)VV;
    float c2 = sqrtf(2.f * inv_n);
    float ps = phisum[k];
    float Tt = ps + inv_n * (tmpsum - tmpsum * ps) + c2 * qsum[k];
    float a = Tt - 1.f;

    if (tid < 128) sP[tid] = 0.f;
    __syncthreads();
    float acc = 0.f;
    for (int i = T; i < DK; i += STR) {
        float w = W[i], ph = phi[i], nz = noise[i];
        float st = ph + inv_n * (MBR * w + 0.1f - tmpsum * ph) + c2 * sqrtf(ph) * nz;
        float p = fmaxf(EPSF, st - a * ph);
        W[i] = p;
        acc += p;
    }
    atomicAdd(&sP[k], acc);
    __syncthreads();
    if (tid < 128) atomicAdd(&P[tid], sP[tid]);
    gbar2();

    float inv = 1.f / fmaxf(EPSF, P[k]);
    for (int i = T; i < DK; i += STR)
        out[i] = W[i] * inv;
}

// ============================================================================
// Fused persistent kernel: split-K reduce + layers 1-2 (NBF blocks)
// ============================================================================
__device__ __forceinline__ void gbar() {
    __threadfence();
    __syncthreads();
    if (threadIdx.x == 0) {
        unsigned g = *(volatile unsigned*)&g_bargen;
        if (atomicAdd(&g_barcnt, 1u) == NBF - 1) {
            g_barcnt = 0u;
            __threadfence();
            atomicAdd(&g_bargen, 1u);
        } else {
            while (*(volatile unsigned*)&g_bargen == g) { __nanosleep(60); }
        }
    }
    __syncthreads();
}

__device__ void small_layer(int D, int K,
                            const float* __restrict__ phi,
                            const float* __restrict__ theta,
                            const float* __restrict__ noise,
                            const float* __restrict__ xin,
                            float* __restrict__ ratio, float* __restrict__ Wb,
                            float* __restrict__ S, float* __restrict__ P,
                            const float* __restrict__ phisum,
                            const float* __restrict__ qsum,
                            float* __restrict__ out, float* __restrict__ xout) {
    const int T = blockIdx.x * NTF + threadIdx.x;
    const int DB = D * BSZ, DK = D * K;

    for (int i = T; i < DB; i += NTOT) {
        int v = i >> 9, b = i & 511;
        float s = 0.f;
        for (int k = 0; k < K; k++) s += phi[v * K + k] * theta[k * BSZ + b];
        float d = fmaxf(s, EPSF);
        float xv = xin[i];
        ratio[i] = digammaf_(d + xv) - digammaf_(d);
    }
    gbar();

    for (int i = T; i < DK; i += NTOT) {
        int v = i / K, k = i - v * K;
        const float* rp = ratio + v * BSZ;
        const float* tp = theta + k * BSZ;
        float s = 0.f;
        for (int b = 0; b < BSZ; b += 4) {
            float4 r4 = *(const float4*)&rp[b];
            float4 t4 = *(const float4*)&tp[b];
            s += r4.x * t4.x + r4.y * t4.y + r4.z * t4.z + r4.w * t4.w;
        }
        float w = phi[i] * s;
        Wb[i] = w;
        atomicAdd(&S[k], w);
    }
    gbar();

    for (int i = T; i < DK; i += NTOT) {
        int k = i % K;
        float s = S[k];
        float inv_n = 1.f / fmaxf(MBR * s, EPSF);
        float tmpsum = MBR * s + 0.1f * (float)D;
        float c2 = sqrtf(2.f * inv_n);
        float psum = phisum[k];
        float Tt = psum + inv_n * (tmpsum - tmpsum * psum) + c2 * qsum[k];
        float a = Tt - 1.f;
        float w = Wb[i], ph = phi[i], nz = noise[i];
        float st = ph + inv_n * (MBR * w + 0.1f - tmpsum * ph) + c2 * sqrtf(ph) * nz;
        float p = fmaxf(EPSF, st - a * ph);
        Wb[i] = p;
        atomicAdd(&P[k], p);
    }
    gbar();

    for (int i = T; i < DK; i += NTOT) {
        int k = i % K;
        out[i] = Wb[i] / fmaxf(EPSF, P[k]);
    }

    if (xout) {
        for (int i = T; i < K * BSZ; i += NTOT) {
            int k = i >> 9, b = i & 511;
            float s = 0.f;
            for (int v = 0; v < D; v++)
                s += phi[v * K + k] * ratio[v * BSZ + b];
            xout[i] = theta[i] * s;
        }
        gbar();
    }
}

__global__ __launch_bounds__(NTF) void fused_small_kernel(
    const float* __restrict__ part, const float* __restrict__ th0,
    const float* __restrict__ phi1, const float* __restrict__ th1,
    const float* __restrict__ nz1,
    const float* __restrict__ phi2, const float* __restrict__ th2,
    const float* __restrict__ nz2,
    float* __restrict__ xa,
    float* __restrict__ ratio1, float* __restrict__ ratio2,
    float* __restrict__ W1, float* __restrict__ W2, float* __restrict__ xb,
    float* __restrict__ S, float* __restrict__ P,
    const float* __restrict__ phisum, const float* __restrict__ qsum,
    float* __restrict__ out1, float* __restrict__ out2) {
    const int T = blockIdx.x * NTF + threadIdx.x;
    const int n = K0 * BSZ;
    for (int i = T; i < n; i += NTOT) {
        float s = 0.f;
        for (int z = 0; z < NZ0; z++) s += part[z * n + i];
        xa[i] = th0[i] * s;
    }
    gbar();
    small_layer(128, 64, phi1, th1, nz1, xa, ratio1, W1,
                S + 128, P + 128, phisum + 128, qsum + 128, out1, xb);
    small_layer(64, 32, phi2, th2, nz2, xb, ratio2, W2,
                S + 256, P + 256, phisum + 256, qsum + 256, out2, nullptr);
}

// ---------------- host orchestration ----------------
extern "C" void kernel_launch(void* const* d_in, const int* in_sizes, int n_in,
                              void* d_out, int out_size) {
    const float* x      = (const float*)d_in[0];
    const float* theta0 = (const float*)d_in[1];
    const float* theta1 = (const float*)d_in[2];
    const float* theta2 = (const float*)d_in[3];
    const float* phi0   = (const float*)d_in[4];
    const float* phi1   = (const float*)d_in[5];
    const float* phi2   = (const float*)d_in[6];
    const float* noise0 = (const float*)d_in[7];
    const float* noise1 = (const float*)d_in[8];
    const float* noise2 = (const float*)d_in[9];
    float* out = (float*)d_out;

    float *ratio, *phiR, *thR, *W, *part, *xa, *xb;
    float *ratio1, *ratio2, *W1, *W2, *S, *P, *phisum, *qsum;
    cudaGetSymbolAddress((void**)&ratio, g_ratio);
    cudaGetSymbolAddress((void**)&phiR, g_phiR);
    cudaGetSymbolAddress((void**)&thR, g_thR);
    cudaGetSymbolAddress((void**)&W, g_W);
    cudaGetSymbolAddress((void**)&part, g_part);
    cudaGetSymbolAddress((void**)&xa, g_xa);
    cudaGetSymbolAddress((void**)&xb, g_xb);
    cudaGetSymbolAddress((void**)&ratio1, g_ratio1);
    cudaGetSymbolAddress((void**)&ratio2, g_ratio2);
    cudaGetSymbolAddress((void**)&W1, g_W1);
    cudaGetSymbolAddress((void**)&W2, g_W2);
    cudaGetSymbolAddress((void**)&S, g_S);
    cudaGetSymbolAddress((void**)&P, g_P);
    cudaGetSymbolAddress((void**)&phisum, g_phisum);
    cudaGetSymbolAddress((void**)&qsum, g_qsum);

    static cudaStream_t s1 = nullptr, s2 = nullptr;
    static cudaEvent_t ev0, evPre, evCs, evG1, evJ;
    if (!s1) {
        cudaStreamCreateWithFlags(&s1, cudaStreamNonBlocking);
        cudaStreamCreateWithFlags(&s2, cudaStreamNonBlocking);
        cudaEventCreateWithFlags(&ev0, cudaEventDisableTiming);
        cudaEventCreateWithFlags(&evPre, cudaEventDisableTiming);
        cudaEventCreateWithFlags(&evCs, cudaEventDisableTiming);
        cudaEventCreateWithFlags(&evG1, cudaEventDisableTiming);
        cudaEventCreateWithFlags(&evJ, cudaEventDisableTiming);
        cudaFuncSetAttribute(ratio_gemm_tc, cudaFuncAttributeMaxDynamicSharedMemorySize,
                             2 * G1_STAGE * 4);
        cudaFuncSetAttribute(wszs_gemm_tc, cudaFuncAttributeMaxDynamicSharedMemorySize,
                             3 * G2_STAGE * 4);
        cudaFuncSetAttribute(xnext_gemm_tc, cudaFuncAttributeMaxDynamicSharedMemorySize,
                             3 * G3_STAGE * 4);
    }

    // ---- fork: zero accumulators first ----
    zero384_kernel<<<1, 384>>>(S, P, phisum, qsum);
    cudaEventRecord(ev0, 0);
    cudaStreamWaitEvent(s1, ev0, 0);
    cudaStreamWaitEvent(s2, ev0, 0);

    // s1: colstats
    colstats3_kernel<<<941, 256, 0, s1>>>(phi0, noise0, phi1, noise1, phi2, noise2,
                                          phisum, qsum);
    cudaEventRecord(evCs, s1);

    // s2: preround
    int n4a = VV * 128 / 4, n4b = 128 * BSZ / 4;
    preround_kernel<<<(n4a + n4b + 255) / 256, 256, 0, s2>>>(
        phi0, (uint32_t*)phiR, n4a, theta0, (uint32_t*)thR, n4b);
    cudaEventRecord(evPre, s2);

    // main: GEMM1 (128x64 tile, 3 CTA/SM)
    cudaStreamWaitEvent(0, evPre, 0);
    ratio_gemm_tc<<<dim3(BSZ / 64, (VV + 127) / 128), 256, 2 * G1_STAGE * 4>>>(
        phiR, thR, x, ratio);
    cudaEventRecord(evG1, 0);

    // ---- branch B on s1: GEMM3 -> fused(reduce + small layers) ----
    cudaStreamWaitEvent(s1, evG1, 0);
    int chunk = (VV + NZ0 - 1) / NZ0;
    xnext_gemm_tc<<<dim3(BSZ / 128, 1, NZ0), 256, 3 * G3_STAGE * 4, s1>>>(
        chunk, phiR, ratio, part);
    fused_small_kernel<<<NBF, NTF, 0, s1>>>(
        part, theta0, phi1, theta1, noise1, phi2, theta2, noise2, xa,
        ratio1, ratio2, W1, W2, xb, S, P, phisum, qsum,
        out + VV * 128, out + VV * 128 + 128 * 64);
    cudaEventRecord(evJ, s1);

    // ---- branch A on main: GEMM2 -> fused step+norm ----
    wszs_gemm_tc<<<dim3(1, (VV + 127) / 128), 256, 3 * G2_STAGE * 4>>>(
        ratio, thR, phi0, W, S);
    cudaStreamWaitEvent(0, evCs, 0);
    step_norm_kernel<<<NSN, 256>>>(W, phi0, noise0, S, phisum, qsum, P, out);

    // ---- join ----
    cudaStreamWaitEvent(0, evJ, 0);
}